// round 14
// baseline (speedup 1.0000x reference)
#include <cuda_runtime.h>
#include <cuda_fp16.h>
#include <cstdint>

#define MAXN 4096

// Per-x-query: wa, wb, wc, bitcast(I)
__device__ float4 g_xw[MAXN];
// Per-y-query: h0, h2, h1, h3*ratio
__device__ float4 g_yw[MAXN];
__device__ int    g_yJ[MAXN];

__device__ __forceinline__ int searchsorted_inner_sm(const float* axis, float q, int n) {
    // searchsorted(axis[1:n-1], q, side='left') on smem-staged axis
    int lo = 0, hi = n - 2;
    while (lo < hi) {
        int mid = (lo + hi) >> 1;
        if (axis[1 + mid] < q) lo = mid + 1; else hi = mid;
    }
    return lo;
}

// Fused setup: axes staged in smem so the binary search is an LDS chain, not a
// DRAM-latency chain. One launch.
__global__ void precompute_fused(const float* __restrict__ xaxis,
                                 const float* __restrict__ yaxis,
                                 const float* __restrict__ xs,
                                 const float* __restrict__ ys,
                                 int n) {
    extern __shared__ float sax[];         // 2*n floats: sx | sy
    float* sx = sax;
    float* sy = sax + n;

    const int tid = threadIdx.x;
    const int k   = blockIdx.x * 256 + tid;

    for (int i = tid; i < n; i += 256) { sx[i] = xaxis[i]; sy[i] = yaxis[i]; }
    __syncthreads();

    if (k >= n) return;

    // ---- x direction ----
    {
        float q = xs[k];
        int I = searchsorted_inner_sm(sx, q, n);
        float x0 = sx[I];
        float x1 = sx[I + 1];
        int i2 = (I + 2 < n) ? I + 2 : n - 1;
        float x2 = sx[i2];
        float dx = x1 - x0;
        float t  = (q - x0) / dx;
        float t2 = t * t, t3 = t2 * t;
        float h0 = 1.0f - 3.0f * t2 + 2.0f * t3;
        float h1 = t - 2.0f * t2 + t3;
        float h2 = 3.0f * t2 - 2.0f * t3;
        float h3 = t3 - t2;
        float r  = dx / (x2 - x1);
        float4 w;
        w.x = h0 - h1;               // weight on S[I]
        w.y = h1 + h2 - h3 * r;      // weight on S[I+1]
        w.z = h3 * r;                // weight on S[I+2]
        w.w = __int_as_float(I);
        g_xw[k] = w;
    }
    // ---- y direction ----
    {
        float q = ys[k];
        int J = searchsorted_inner_sm(sy, q, n);
        float y0 = sy[J];
        float y1 = sy[J + 1];
        int j2 = (J + 2 < n) ? J + 2 : n - 1;
        float y2 = sy[j2];
        float dy = y1 - y0;
        float t  = (q - y0) / dy;
        float t2 = t * t, t3 = t2 * t;
        float h0 = 1.0f - 3.0f * t2 + 2.0f * t3;
        float h1 = t - 2.0f * t2 + t3;
        float h2 = 3.0f * t2 - 2.0f * t3;
        float h3 = t3 - t2;
        float r  = dy / (y2 - y1);
        float4 w;
        w.x = h0;        // weight on out[.., J]
        w.y = h2;        // weight on out[.., J+1]
        w.z = h1;        // weight on (S[J+1,k]-S[J,k])
        w.w = h3 * r;    // weight on (S[J+2,k]-S[J+1,k])
        g_yw[k] = w;
        g_yJ[k] = J;
    }
}

__device__ __forceinline__ float2 h2f(unsigned u) {
    __half2 h = *reinterpret_cast<__half2*>(&u);
    return __half22float2(h);
}

// ─────────────── Specialized N=1024, 4-batches-per-CTA, fp16 gather ─────────
// 512 threads/CTA, 2 k-slots per thread. One CTA handles output row `my` for
// 4 consecutive batches. Smem stores the gathered array rowC in fp16,
// batch-interleaved: 8 bytes per index hold all 4 batches, so each tap is one
// LDS.64 — half the gather bytes (and half the conflict replays) of fp32.
// The y-slope D term stays fp32 in registers, bounding the rounding error to
// the fp16 quantization of C (~1.5e-4 relative).
__global__ __launch_bounds__(512) void hermite2d_n1024_b4(
    const float* __restrict__ signal,
    float* __restrict__ out) {
    __shared__ __align__(8) uint2 rowCh[1024];   // 8 KB: (half2 b01, half2 b23)

    const int t  = threadIdx.x;            // 0..511
    const int bm = blockIdx.x;
    const int bq = bm >> 10;               // batch quad
    const int my = bm & 1023;

    const int    J  = g_yJ[my];
    const float4 yw = g_yw[my];

    // weight loads are independent of smem — issue before staging/barrier
    const float4 w0 = g_xw[t];
    const float4 w1 = g_xw[t + 512];

    const float* __restrict__ base0 = signal + (((size_t)(4 * bq + 0) << 10) + (size_t)J) * 1024u;
    const float* __restrict__ base1 = base0 + (1u << 20);
    const float* __restrict__ base2 = base0 + (2u << 20);
    const float* __restrict__ base3 = base0 + (3u << 20);

    float D[4][2];                         // [bb][j] coalesced y-slope term (fp32)

    #pragma unroll
    for (int j = 0; j < 2; j++) {
        const int k = t + 512 * j;
        float C0, C1, C2, C3;
        {
            float a = base0[k], c = base0[1024 + k], e = base0[2048 + k];
            C0 = yw.x * a + yw.y * c;
            D[0][j] = yw.z * (c - a) + yw.w * (e - c);
        }
        {
            float a = base1[k], c = base1[1024 + k], e = base1[2048 + k];
            C1 = yw.x * a + yw.y * c;
            D[1][j] = yw.z * (c - a) + yw.w * (e - c);
        }
        {
            float a = base2[k], c = base2[1024 + k], e = base2[2048 + k];
            C2 = yw.x * a + yw.y * c;
            D[2][j] = yw.z * (c - a) + yw.w * (e - c);
        }
        {
            float a = base3[k], c = base3[1024 + k], e = base3[2048 + k];
            C3 = yw.x * a + yw.y * c;
            D[3][j] = yw.z * (c - a) + yw.w * (e - c);
        }
        __half2 h01 = __floats2half2_rn(C0, C1);
        __half2 h23 = __floats2half2_rn(C2, C3);
        uint2 packed;
        packed.x = *reinterpret_cast<unsigned*>(&h01);
        packed.y = *reinterpret_cast<unsigned*>(&h23);
        rowCh[k] = packed;                 // STS.64, conflict-free
    }
    __syncthreads();

    float* __restrict__ o0 = out + (((size_t)(4 * bq + 0) << 10) + (size_t)my) * 1024u;
    float* __restrict__ o1 = o0 + (1u << 20);
    float* __restrict__ o2 = o0 + (2u << 20);
    float* __restrict__ o3 = o0 + (3u << 20);

    {
        const int k = t;
        const int I = __float_as_int(w0.w);
        const uint2 v0 = rowCh[I];         // LDS.64: taps for all 4 batches
        const uint2 v1 = rowCh[I + 1];
        const uint2 v2 = rowCh[I + 2];
        const float2 a0 = h2f(v0.x), b0 = h2f(v0.y);
        const float2 a1 = h2f(v1.x), b1 = h2f(v1.y);
        const float2 a2 = h2f(v2.x), b2 = h2f(v2.y);
        o0[k] = w0.x * a0.x + w0.y * a1.x + w0.z * a2.x + D[0][0];
        o1[k] = w0.x * a0.y + w0.y * a1.y + w0.z * a2.y + D[1][0];
        o2[k] = w0.x * b0.x + w0.y * b1.x + w0.z * b2.x + D[2][0];
        o3[k] = w0.x * b0.y + w0.y * b1.y + w0.z * b2.y + D[3][0];
    }
    {
        const int k = t + 512;
        const int I = __float_as_int(w1.w);
        const uint2 v0 = rowCh[I];
        const uint2 v1 = rowCh[I + 1];
        const uint2 v2 = rowCh[I + 2];
        const float2 a0 = h2f(v0.x), b0 = h2f(v0.y);
        const float2 a1 = h2f(v1.x), b1 = h2f(v1.y);
        const float2 a2 = h2f(v2.x), b2 = h2f(v2.y);
        o0[k] = w1.x * a0.x + w1.y * a1.x + w1.z * a2.x + D[0][1];
        o1[k] = w1.x * a0.y + w1.y * a1.y + w1.z * a2.y + D[1][1];
        o2[k] = w1.x * b0.x + w1.y * b1.x + w1.z * b2.x + D[2][1];
        o3[k] = w1.x * b0.y + w1.y * b1.y + w1.z * b2.y + D[3][1];
    }
}

// ─────────────── Specialized N=1024, 1 row per CTA (B % 4 != 0) ─────────────
__global__ __launch_bounds__(256) void hermite2d_n1024(
    const float* __restrict__ signal,
    float* __restrict__ out) {
    __shared__ float rowC[1024];

    const int t  = threadIdx.x;
    const int bm = blockIdx.x;
    const int b  = bm >> 10;
    const int my = bm & 1023;

    const int    J  = g_yJ[my];
    const float4 yw = g_yw[my];

    const float* __restrict__ base = signal + (((size_t)b << 10) + (size_t)J) * 1024u;

    float D[4];
    #pragma unroll
    for (int j = 0; j < 4; j++) {
        const int k = t + 256 * j;
        float a = base[k];
        float c = base[1024 + k];
        float e = base[2048 + k];
        rowC[k] = yw.x * a + yw.y * c;
        D[j]    = yw.z * (c - a) + yw.w * (e - c);
    }
    __syncthreads();

    float* __restrict__ orow = out + (((size_t)b << 10) + (size_t)my) * 1024u;
    #pragma unroll
    for (int j = 0; j < 4; j++) {
        const int k = t + 256 * j;
        const float4 w = g_xw[k];
        const int I = __float_as_int(w.w);
        orow[k] = w.x * rowC[I] + w.y * rowC[I + 1] + w.z * rowC[I + 2] + D[j];
    }
}

// ───────────────────────── Generic fallback (any n % 4 == 0) ─────────────────
__global__ __launch_bounds__(256) void hermite2d_generic(
    const float* __restrict__ signal,
    float* __restrict__ out,
    int n) {
    extern __shared__ float sm[];          // 2*n floats
    float* rowC = sm;
    float* rowD = sm + n;

    int bm = blockIdx.x;
    int b  = bm / n;
    int my = bm - b * n;

    int    J  = g_yJ[my];
    float4 yw = g_yw[my];

    const float* base = signal + ((size_t)b * n + J) * (size_t)n;
    int nv = n >> 2;
    const float4* srcJ  = reinterpret_cast<const float4*>(base);
    const float4* srcJ1 = reinterpret_cast<const float4*>(base + n);
    const float4* srcJ2 = reinterpret_cast<const float4*>(base + 2 * (size_t)n);
    float4* dstC = reinterpret_cast<float4*>(rowC);
    float4* dstD = reinterpret_cast<float4*>(rowD);
    for (int i = threadIdx.x; i < nv; i += blockDim.x) {
        float4 a = srcJ[i];
        float4 c = srcJ1[i];
        float4 e = srcJ2[i];
        float4 C, Dv;
        C.x = yw.x * a.x + yw.y * c.x;
        C.y = yw.x * a.y + yw.y * c.y;
        C.z = yw.x * a.z + yw.y * c.z;
        C.w = yw.x * a.w + yw.y * c.w;
        Dv.x = yw.z * (c.x - a.x) + yw.w * (e.x - c.x);
        Dv.y = yw.z * (c.y - a.y) + yw.w * (e.y - c.y);
        Dv.z = yw.z * (c.z - a.z) + yw.w * (e.z - c.z);
        Dv.w = yw.z * (c.w - a.w) + yw.w * (e.w - c.w);
        dstC[i] = C;
        dstD[i] = Dv;
    }
    __syncthreads();

    float* orow = out + ((size_t)b * n + my) * (size_t)n;
    for (int k = threadIdx.x; k < n; k += blockDim.x) {
        float4 xw = g_xw[k];
        int I = __float_as_int(xw.w);
        orow[k] = xw.x * rowC[I] + xw.y * rowC[I + 1] + xw.z * rowC[I + 2] + rowD[k];
    }
}

extern "C" void kernel_launch(void* const* d_in, const int* in_sizes, int n_in,
                              void* d_out, int out_size) {
    const float* xaxis  = (const float*)d_in[0];
    const float* yaxis  = (const float*)d_in[1];
    const float* signal = (const float*)d_in[2];
    const float* xs     = (const float*)d_in[3];
    const float* ys     = (const float*)d_in[4];
    float* out = (float*)d_out;

    int n = in_sizes[0];                 // N (square grid, Mx = My = N)
    int B = in_sizes[2] / (n * n);       // batch

    size_t smem_pre = 2 * (size_t)n * sizeof(float);
    precompute_fused<<<(n + 255) / 256, 256, smem_pre>>>(xaxis, yaxis, xs, ys, n);

    if (n == 1024 && (B % 4) == 0) {
        hermite2d_n1024_b4<<<(B / 4) * n, 512>>>(signal, out);
    } else if (n == 1024) {
        hermite2d_n1024<<<B * n, 256>>>(signal, out);
    } else {
        size_t smem = 2 * (size_t)n * sizeof(float);
        hermite2d_generic<<<B * n, 256, smem>>>(signal, out, n);
    }
}

// round 15
// speedup vs baseline: 1.0014x; 1.0014x over previous
#include <cuda_runtime.h>
#include <cuda_fp16.h>
#include <cstdint>

#define MAXN 4096

// Per-x-query: wa, wb, wc, bitcast(I)
__device__ float4 g_xw[MAXN];
// Per-y-query: h0, h2, h1, h3*ratio
__device__ float4 g_yw[MAXN];
__device__ int    g_yJ[MAXN];

__device__ __forceinline__ int searchsorted_inner_sm(const float* axis, float q, int n) {
    // searchsorted(axis[1:n-1], q, side='left') on smem-staged axis
    int lo = 0, hi = n - 2;
    while (lo < hi) {
        int mid = (lo + hi) >> 1;
        if (axis[1 + mid] < q) lo = mid + 1; else hi = mid;
    }
    return lo;
}

// Fused setup: axes staged in smem so the binary search is an LDS chain, not a
// DRAM-latency chain. One launch.
__global__ void precompute_fused(const float* __restrict__ xaxis,
                                 const float* __restrict__ yaxis,
                                 const float* __restrict__ xs,
                                 const float* __restrict__ ys,
                                 int n) {
    extern __shared__ float sax[];         // 2*n floats: sx | sy
    float* sx = sax;
    float* sy = sax + n;

    const int tid = threadIdx.x;
    const int k   = blockIdx.x * 256 + tid;

    for (int i = tid; i < n; i += 256) { sx[i] = xaxis[i]; sy[i] = yaxis[i]; }
    __syncthreads();

    if (k >= n) return;

    // ---- x direction ----
    {
        float q = xs[k];
        int I = searchsorted_inner_sm(sx, q, n);
        float x0 = sx[I];
        float x1 = sx[I + 1];
        int i2 = (I + 2 < n) ? I + 2 : n - 1;
        float x2 = sx[i2];
        float dx = x1 - x0;
        float t  = (q - x0) / dx;
        float t2 = t * t, t3 = t2 * t;
        float h0 = 1.0f - 3.0f * t2 + 2.0f * t3;
        float h1 = t - 2.0f * t2 + t3;
        float h2 = 3.0f * t2 - 2.0f * t3;
        float h3 = t3 - t2;
        float r  = dx / (x2 - x1);
        float4 w;
        w.x = h0 - h1;               // weight on S[I]
        w.y = h1 + h2 - h3 * r;      // weight on S[I+1]
        w.z = h3 * r;                // weight on S[I+2]
        w.w = __int_as_float(I);
        g_xw[k] = w;
    }
    // ---- y direction ----
    {
        float q = ys[k];
        int J = searchsorted_inner_sm(sy, q, n);
        float y0 = sy[J];
        float y1 = sy[J + 1];
        int j2 = (J + 2 < n) ? J + 2 : n - 1;
        float y2 = sy[j2];
        float dy = y1 - y0;
        float t  = (q - y0) / dy;
        float t2 = t * t, t3 = t2 * t;
        float h0 = 1.0f - 3.0f * t2 + 2.0f * t3;
        float h1 = t - 2.0f * t2 + t3;
        float h2 = 3.0f * t2 - 2.0f * t3;
        float h3 = t3 - t2;
        float r  = dy / (y2 - y1);
        float4 w;
        w.x = h0;        // weight on out[.., J]
        w.y = h2;        // weight on out[.., J+1]
        w.z = h1;        // weight on (S[J+1,k]-S[J,k])
        w.w = h3 * r;    // weight on (S[J+2,k]-S[J+1,k])
        g_yw[k] = w;
        g_yJ[k] = J;
    }
}

__device__ __forceinline__ float2 h2f(unsigned u) {
    __half2 h = *reinterpret_cast<__half2*>(&u);
    return __half22float2(h);
}

// ─────────────── Specialized N=1024, 4-batches-per-CTA, fp16 gather ─────────
// 512 threads/CTA, 2 k-slots per thread. One CTA handles output row `my` for
// 4 consecutive batches. Smem stores the gathered array rowC in fp16,
// batch-interleaved: 8 bytes per index hold all 4 batches, so each tap is one
// LDS.64 — half the gather bytes (and half the conflict replays) of fp32.
// The y-slope D term stays fp32 in registers, bounding the rounding error to
// the fp16 quantization of C (~1.5e-4 relative).
__global__ __launch_bounds__(512) void hermite2d_n1024_b4(
    const float* __restrict__ signal,
    float* __restrict__ out) {
    __shared__ __align__(8) uint2 rowCh[1024];   // 8 KB: (half2 b01, half2 b23)

    const int t  = threadIdx.x;            // 0..511
    const int bm = blockIdx.x;
    const int bq = bm >> 10;               // batch quad
    const int my = bm & 1023;

    const int    J  = g_yJ[my];
    const float4 yw = g_yw[my];

    // weight loads are independent of smem — issue before staging/barrier
    const float4 w0 = g_xw[t];
    const float4 w1 = g_xw[t + 512];

    const float* __restrict__ base0 = signal + (((size_t)(4 * bq + 0) << 10) + (size_t)J) * 1024u;
    const float* __restrict__ base1 = base0 + (1u << 20);
    const float* __restrict__ base2 = base0 + (2u << 20);
    const float* __restrict__ base3 = base0 + (3u << 20);

    float D[4][2];                         // [bb][j] coalesced y-slope term (fp32)

    #pragma unroll
    for (int j = 0; j < 2; j++) {
        const int k = t + 512 * j;
        float C0, C1, C2, C3;
        {
            float a = base0[k], c = base0[1024 + k], e = base0[2048 + k];
            C0 = yw.x * a + yw.y * c;
            D[0][j] = yw.z * (c - a) + yw.w * (e - c);
        }
        {
            float a = base1[k], c = base1[1024 + k], e = base1[2048 + k];
            C1 = yw.x * a + yw.y * c;
            D[1][j] = yw.z * (c - a) + yw.w * (e - c);
        }
        {
            float a = base2[k], c = base2[1024 + k], e = base2[2048 + k];
            C2 = yw.x * a + yw.y * c;
            D[2][j] = yw.z * (c - a) + yw.w * (e - c);
        }
        {
            float a = base3[k], c = base3[1024 + k], e = base3[2048 + k];
            C3 = yw.x * a + yw.y * c;
            D[3][j] = yw.z * (c - a) + yw.w * (e - c);
        }
        __half2 h01 = __floats2half2_rn(C0, C1);
        __half2 h23 = __floats2half2_rn(C2, C3);
        uint2 packed;
        packed.x = *reinterpret_cast<unsigned*>(&h01);
        packed.y = *reinterpret_cast<unsigned*>(&h23);
        rowCh[k] = packed;                 // STS.64, conflict-free
    }
    __syncthreads();

    float* __restrict__ o0 = out + (((size_t)(4 * bq + 0) << 10) + (size_t)my) * 1024u;
    float* __restrict__ o1 = o0 + (1u << 20);
    float* __restrict__ o2 = o0 + (2u << 20);
    float* __restrict__ o3 = o0 + (3u << 20);

    {
        const int k = t;
        const int I = __float_as_int(w0.w);
        const uint2 v0 = rowCh[I];         // LDS.64: taps for all 4 batches
        const uint2 v1 = rowCh[I + 1];
        const uint2 v2 = rowCh[I + 2];
        const float2 a0 = h2f(v0.x), b0 = h2f(v0.y);
        const float2 a1 = h2f(v1.x), b1 = h2f(v1.y);
        const float2 a2 = h2f(v2.x), b2 = h2f(v2.y);
        o0[k] = w0.x * a0.x + w0.y * a1.x + w0.z * a2.x + D[0][0];
        o1[k] = w0.x * a0.y + w0.y * a1.y + w0.z * a2.y + D[1][0];
        o2[k] = w0.x * b0.x + w0.y * b1.x + w0.z * b2.x + D[2][0];
        o3[k] = w0.x * b0.y + w0.y * b1.y + w0.z * b2.y + D[3][0];
    }
    {
        const int k = t + 512;
        const int I = __float_as_int(w1.w);
        const uint2 v0 = rowCh[I];
        const uint2 v1 = rowCh[I + 1];
        const uint2 v2 = rowCh[I + 2];
        const float2 a0 = h2f(v0.x), b0 = h2f(v0.y);
        const float2 a1 = h2f(v1.x), b1 = h2f(v1.y);
        const float2 a2 = h2f(v2.x), b2 = h2f(v2.y);
        o0[k] = w1.x * a0.x + w1.y * a1.x + w1.z * a2.x + D[0][1];
        o1[k] = w1.x * a0.y + w1.y * a1.y + w1.z * a2.y + D[1][1];
        o2[k] = w1.x * b0.x + w1.y * b1.x + w1.z * b2.x + D[2][1];
        o3[k] = w1.x * b0.y + w1.y * b1.y + w1.z * b2.y + D[3][1];
    }
}

// ─────────────── Specialized N=1024, 1 row per CTA (B % 4 != 0) ─────────────
__global__ __launch_bounds__(256) void hermite2d_n1024(
    const float* __restrict__ signal,
    float* __restrict__ out) {
    __shared__ float rowC[1024];

    const int t  = threadIdx.x;
    const int bm = blockIdx.x;
    const int b  = bm >> 10;
    const int my = bm & 1023;

    const int    J  = g_yJ[my];
    const float4 yw = g_yw[my];

    const float* __restrict__ base = signal + (((size_t)b << 10) + (size_t)J) * 1024u;

    float D[4];
    #pragma unroll
    for (int j = 0; j < 4; j++) {
        const int k = t + 256 * j;
        float a = base[k];
        float c = base[1024 + k];
        float e = base[2048 + k];
        rowC[k] = yw.x * a + yw.y * c;
        D[j]    = yw.z * (c - a) + yw.w * (e - c);
    }
    __syncthreads();

    float* __restrict__ orow = out + (((size_t)b << 10) + (size_t)my) * 1024u;
    #pragma unroll
    for (int j = 0; j < 4; j++) {
        const int k = t + 256 * j;
        const float4 w = g_xw[k];
        const int I = __float_as_int(w.w);
        orow[k] = w.x * rowC[I] + w.y * rowC[I + 1] + w.z * rowC[I + 2] + D[j];
    }
}

// ───────────────────────── Generic fallback (any n % 4 == 0) ─────────────────
__global__ __launch_bounds__(256) void hermite2d_generic(
    const float* __restrict__ signal,
    float* __restrict__ out,
    int n) {
    extern __shared__ float sm[];          // 2*n floats
    float* rowC = sm;
    float* rowD = sm + n;

    int bm = blockIdx.x;
    int b  = bm / n;
    int my = bm - b * n;

    int    J  = g_yJ[my];
    float4 yw = g_yw[my];

    const float* base = signal + ((size_t)b * n + J) * (size_t)n;
    int nv = n >> 2;
    const float4* srcJ  = reinterpret_cast<const float4*>(base);
    const float4* srcJ1 = reinterpret_cast<const float4*>(base + n);
    const float4* srcJ2 = reinterpret_cast<const float4*>(base + 2 * (size_t)n);
    float4* dstC = reinterpret_cast<float4*>(rowC);
    float4* dstD = reinterpret_cast<float4*>(rowD);
    for (int i = threadIdx.x; i < nv; i += blockDim.x) {
        float4 a = srcJ[i];
        float4 c = srcJ1[i];
        float4 e = srcJ2[i];
        float4 C, Dv;
        C.x = yw.x * a.x + yw.y * c.x;
        C.y = yw.x * a.y + yw.y * c.y;
        C.z = yw.x * a.z + yw.y * c.z;
        C.w = yw.x * a.w + yw.y * c.w;
        Dv.x = yw.z * (c.x - a.x) + yw.w * (e.x - c.x);
        Dv.y = yw.z * (c.y - a.y) + yw.w * (e.y - c.y);
        Dv.z = yw.z * (c.z - a.z) + yw.w * (e.z - c.z);
        Dv.w = yw.z * (c.w - a.w) + yw.w * (e.w - c.w);
        dstC[i] = C;
        dstD[i] = Dv;
    }
    __syncthreads();

    float* orow = out + ((size_t)b * n + my) * (size_t)n;
    for (int k = threadIdx.x; k < n; k += blockDim.x) {
        float4 xw = g_xw[k];
        int I = __float_as_int(xw.w);
        orow[k] = xw.x * rowC[I] + xw.y * rowC[I + 1] + xw.z * rowC[I + 2] + rowD[k];
    }
}

extern "C" void kernel_launch(void* const* d_in, const int* in_sizes, int n_in,
                              void* d_out, int out_size) {
    const float* xaxis  = (const float*)d_in[0];
    const float* yaxis  = (const float*)d_in[1];
    const float* signal = (const float*)d_in[2];
    const float* xs     = (const float*)d_in[3];
    const float* ys     = (const float*)d_in[4];
    float* out = (float*)d_out;

    int n = in_sizes[0];                 // N (square grid, Mx = My = N)
    int B = in_sizes[2] / (n * n);       // batch

    size_t smem_pre = 2 * (size_t)n * sizeof(float);
    precompute_fused<<<(n + 255) / 256, 256, smem_pre>>>(xaxis, yaxis, xs, ys, n);

    if (n == 1024 && (B % 4) == 0) {
        hermite2d_n1024_b4<<<(B / 4) * n, 512>>>(signal, out);
    } else if (n == 1024) {
        hermite2d_n1024<<<B * n, 256>>>(signal, out);
    } else {
        size_t smem = 2 * (size_t)n * sizeof(float);
        hermite2d_generic<<<B * n, 256, smem>>>(signal, out, n);
    }
}